// round 17
// baseline (speedup 1.0000x reference)
#include <cuda_runtime.h>
#include <cuda_bf16.h>
#include <cstdint>
#include <math.h>

// =====================================================================
// NN_Model_19748259627524 — Bayesian NN sampling forward pass.
// Both stages on HMMA (mma.sync bf16), exact-compensated 3-term splits.
// R13: stage-1 C-frag == stage-2 A-frag register trick (no A smem).
// R14: process 2 m per iteration; stage-2 B fragments loaded once per
//      c-tile serve both m (B-LDSM/m halved); 1 barrier per 2 m;
//      bias via LDS at store (register relief); 4-buffer w0split.
// R15: identical resubmit of R14 (container infra failure, no signal).
// =====================================================================

#define JAX_PARTITIONABLE 1

#define K_N     16384
#define K_D     17
#define K_H     64
#define K_M     100
#define K_LENM  1088
#define K_MPRI  65
#define PRED_ELEMS 163840000LL   // 16384*100*100

__device__ float g_w0[K_M * K_LENM];   // [m][i], i = d*64+h
__device__ float g_w1[K_MPRI * K_M];   // [d][c]

// ---------------------------------------------------------------------
// threefry2x32 (JAX rotation schedule)
// ---------------------------------------------------------------------
__device__ __forceinline__ void tf2x32(unsigned k0, unsigned k1,
                                       unsigned x0, unsigned x1,
                                       unsigned &o0, unsigned &o1) {
  unsigned ks2 = k0 ^ k1 ^ 0x1BD11BDAu;
  x0 += k0; x1 += k1;
#define TF_R(r) { x0 += x1; x1 = (x1 << (r)) | (x1 >> (32 - (r))); x1 ^= x0; }
  TF_R(13) TF_R(15) TF_R(26) TF_R(6)  x0 += k1;  x1 += ks2 + 1u;
  TF_R(17) TF_R(29) TF_R(16) TF_R(24) x0 += ks2; x1 += k0 + 2u;
  TF_R(13) TF_R(15) TF_R(26) TF_R(6)  x0 += k0;  x1 += k1 + 3u;
  TF_R(17) TF_R(29) TF_R(16) TF_R(24) x0 += k1;  x1 += ks2 + 4u;
  TF_R(13) TF_R(15) TF_R(26) TF_R(6)  x0 += ks2; x1 += k0 + 5u;
#undef TF_R
  o0 = x0; o1 = x1;
}

__device__ __forceinline__ void get_key(unsigned which, unsigned &s0, unsigned &s1) {
#if JAX_PARTITIONABLE
  tf2x32(0u, 42u, 0u, which, s0, s1);
#else
  unsigned a0, a1, b0, b1;
  tf2x32(0u, 42u, 0u, 2u, a0, a1);
  tf2x32(0u, 42u, 1u, 3u, b0, b1);
  if (which == 0u) { s0 = a0; s1 = b0; } else { s0 = a1; s1 = b1; }
#endif
}

__device__ __forceinline__ float jax_normal(unsigned k0, unsigned k1,
                                            unsigned idx, unsigned half) {
  unsigned a, b, bits;
#if JAX_PARTITIONABLE
  tf2x32(k0, k1, 0u, idx, a, b);
  bits = a ^ b;
#else
  if (idx < half) { tf2x32(k0, k1, idx, idx + half, a, b); bits = a; }
  else            { tf2x32(k0, k1, idx - half, idx, a, b); bits = b; }
#endif
  float u = __uint_as_float((bits >> 9) | 0x3f800000u) - 1.0f;
  float v = fmaf(u, 1.99999994f, -0.99999994f);
  v = fmaxf(v, -0.99999994f);
  return 1.41421356237f * erfinvf(v);
}

// ---------------------------------------------------------------------
// merged setup kernel
// ---------------------------------------------------------------------
__global__ void setup_kernel(const float* __restrict__ ms,
                             float* __restrict__ out, int out_size) {
  int j = blockIdx.x * blockDim.x + threadIdx.x;
  if (j < K_LENM * K_M) {
    unsigned s0, s1; get_key(0u, s0, s1);
    float eps = jax_normal(s0, s1, (unsigned)j, 54400u);
    int i = j / K_M;
    int m = j - i * K_M;
    float vv = fabsf(ms[1153 + i]) + 1e-6f;
    g_w0[m * K_LENM + i] = fmaf(eps, sqrtf(vv), ms[i]);
  }
  if (j < K_MPRI * K_M) {
    unsigned s0, s1; get_key(1u, s0, s1);
    float eps = jax_normal(s0, s1, (unsigned)j, 3250u);
    int d = j / K_M;
    float vv = fabsf(ms[2241 + d]) + 1e-6f;
    g_w1[j] = fmaf(eps, sqrtf(vv), ms[1088 + d]);
  }
  if ((long long)out_size >= PRED_ELEMS + 2306LL) {
    size_t P = (size_t)PRED_ELEMS;
    if (j < 1088) {
      out[P + j]        = ms[j];
      out[P + 1088 + j] = fabsf(ms[1153 + j]) + 1e-6f;
    }
    if (j < 65) {
      out[P + 2176 + j] = ms[1088 + j];
      out[P + 2241 + j] = fabsf(ms[2241 + j]) + 1e-6f;
    }
  }
}

// ---------------------------------------------------------------------
// warp-MMA helpers
// ---------------------------------------------------------------------
__device__ __forceinline__ uint32_t smem_u32(const void* p) {
  uint32_t a;
  asm("{ .reg .u64 t; cvta.to.shared.u64 t, %1; cvt.u32.u64 %0, t; }"
      : "=r"(a) : "l"(p));
  return a;
}

__device__ __forceinline__ void ldsm_x4(uint32_t &r0, uint32_t &r1,
                                        uint32_t &r2, uint32_t &r3,
                                        uint32_t addr) {
  asm volatile("ldmatrix.sync.aligned.m8n8.x4.shared.b16 {%0,%1,%2,%3}, [%4];"
               : "=r"(r0), "=r"(r1), "=r"(r2), "=r"(r3) : "r"(addr));
}

__device__ __forceinline__ void mma_bf16(float &c0, float &c1, float &c2, float &c3,
                                         uint32_t a0, uint32_t a1, uint32_t a2, uint32_t a3,
                                         uint32_t b0, uint32_t b1) {
  asm volatile(
      "mma.sync.aligned.m16n8k16.row.col.f32.bf16.bf16.f32 "
      "{%0,%1,%2,%3}, {%4,%5,%6,%7}, {%8,%9}, {%0,%1,%2,%3};"
      : "+f"(c0), "+f"(c1), "+f"(c2), "+f"(c3)
      : "r"(a0), "r"(a1), "r"(a2), "r"(a3), "r"(b0), "r"(b1));
}

__device__ __forceinline__ uint32_t packbf2(float a, float b) {
  __nv_bfloat162 t;
  t.x = __float2bfloat16(a);
  t.y = __float2bfloat16(b);
  return *(uint32_t*)&t;
}

// ---------------------------------------------------------------------
// smem layout (bytes)
// ---------------------------------------------------------------------
#define ASTRIDE 272        // B' row stride (128 k bf16 + pad)
#define XSTRIDE 144        // xsplit/w0split row stride (64 k bf16 + pad)
#define SM_B    0          // 104*272 = 28288   B' = [W1h|W1l] per c
#define SM_XS   28416      // 128*144 = 18432   xsplit = [xh|xl] per n
#define SM_W0S  46848      // 4 x 64*144 = 36864 (pair ping-pong)
#define SM_BIAS 83712      // 128*4 = 512
#define SM_TOTAL 84224

#define W0SBUF  9216       // 64*144

// stage-1: zacc = [xh|xl] @ [wh|wl] (3 terms), then relu+split -> ah/al
__device__ __forceinline__ void stage1_to_frags(
    const uint32_t wb, const uint32_t (&xa)[2][2][4],
    uint32_t (&ah)[4][4], uint32_t (&al)[4][4]) {
  float zacc[8][4];
#pragma unroll
  for (int j = 0; j < 8; ++j)
#pragma unroll
    for (int q = 0; q < 4; ++q) zacc[j][q] = 0.0f;

#pragma unroll
  for (int j = 0; j < 8; ++j) {
    uint32_t bh[4], bl[4];
    ldsm_x4(bh[0], bh[1], bh[2], bh[3], wb + (uint32_t)(j * 8 * XSTRIDE));
    ldsm_x4(bl[0], bl[1], bl[2], bl[3], wb + (uint32_t)(j * 8 * XSTRIDE + 64));
    mma_bf16(zacc[j][0], zacc[j][1], zacc[j][2], zacc[j][3],
             xa[0][0][0], xa[0][0][1], xa[0][0][2], xa[0][0][3], bh[0], bh[1]);
    mma_bf16(zacc[j][0], zacc[j][1], zacc[j][2], zacc[j][3],
             xa[0][1][0], xa[0][1][1], xa[0][1][2], xa[0][1][3], bh[2], bh[3]);
    mma_bf16(zacc[j][0], zacc[j][1], zacc[j][2], zacc[j][3],
             xa[1][0][0], xa[1][0][1], xa[1][0][2], xa[1][0][3], bh[0], bh[1]);
    mma_bf16(zacc[j][0], zacc[j][1], zacc[j][2], zacc[j][3],
             xa[1][1][0], xa[1][1][1], xa[1][1][2], xa[1][1][3], bh[2], bh[3]);
    mma_bf16(zacc[j][0], zacc[j][1], zacc[j][2], zacc[j][3],
             xa[0][0][0], xa[0][0][1], xa[0][0][2], xa[0][0][3], bl[0], bl[1]);
    mma_bf16(zacc[j][0], zacc[j][1], zacc[j][2], zacc[j][3],
             xa[0][1][0], xa[0][1][1], xa[0][1][2], xa[0][1][3], bl[2], bl[3]);
  }

  // relu + hi/lo split in registers; C-frag(m16n8) == A-frag(m16n8k16)
#pragma unroll
  for (int ks = 0; ks < 4; ++ks) {
#pragma unroll
    for (int hf = 0; hf < 2; ++hf) {
      const int j2 = 2 * ks + hf;
      float z0 = fmaxf(zacc[j2][0], 0.0f);
      float z1 = fmaxf(zacc[j2][1], 0.0f);
      float z2 = fmaxf(zacc[j2][2], 0.0f);
      float z3 = fmaxf(zacc[j2][3], 0.0f);
      __nv_bfloat16 h0 = __float2bfloat16(z0);
      __nv_bfloat16 h1 = __float2bfloat16(z1);
      __nv_bfloat16 h2 = __float2bfloat16(z2);
      __nv_bfloat16 h3 = __float2bfloat16(z3);
      ah[ks][hf * 2 + 0] = packbf2(z0, z1);
      ah[ks][hf * 2 + 1] = packbf2(z2, z3);
      al[ks][hf * 2 + 0] = packbf2(z0 - __bfloat162float(h0),
                                   z1 - __bfloat162float(h1));
      al[ks][hf * 2 + 1] = packbf2(z2 - __bfloat162float(h2),
                                   z3 - __bfloat162float(h3));
    }
  }
}

__global__ void __launch_bounds__(256, 2)
pred_kernel(const float* __restrict__ x, float* __restrict__ out) {
  extern __shared__ char smem[];
  const uint32_t sbase = smem_u32(smem);
  float* bias_s = (float*)(smem + SM_BIAS);

  const int tid  = threadIdx.x;
  const int wid  = tid >> 5;
  const int lane = tid & 31;
  const int n0 = blockIdx.x * 128;
  const int mbase = blockIdx.y * 25;

  // ---- zero xsplit + 4 w0split buffers (55296 B contiguous) ----
  {
    int4* z = (int4*)(smem + SM_XS);
    for (int k = tid; k < 3456; k += 256) z[k] = make_int4(0, 0, 0, 0);
  }
  __syncthreads();

  // ---- build B' = [W1h | W1l] rows c (104 rows, zero-pad c>=100) ----
  for (int idx = tid; idx < 104 * 32; idx += 256) {
    int c = idx >> 5;
    int h0 = (idx & 31) * 2;
    float v0 = (c < K_M) ? g_w1[(h0 + 1) * K_M + c] : 0.0f;
    float v1 = (c < K_M) ? g_w1[(h0 + 2) * K_M + c] : 0.0f;
    __nv_bfloat162 h2, l2;
    h2.x = __float2bfloat16(v0);
    h2.y = __float2bfloat16(v1);
    l2.x = __float2bfloat16(v0 - __bfloat162float(h2.x));
    l2.y = __float2bfloat16(v1 - __bfloat162float(h2.y));
    char* row = smem + SM_B + c * ASTRIDE;
    *(__nv_bfloat162*)(row + h0 * 2)       = h2;
    *(__nv_bfloat162*)(row + 128 + h0 * 2) = l2;
  }
  if (tid < 128) bias_s[tid] = (tid < K_M) ? g_w1[tid] : 0.0f;

  // ---- build xsplit: [n][k]  xh at d*2, xl at 64+d*2 ----
  for (int idx = tid; idx < 128 * K_D; idx += 256) {
    int n = idx / K_D, d = idx - n * K_D;
    float v = x[(size_t)n0 * K_D + idx];
    __nv_bfloat16 h = __float2bfloat16(v);
    __nv_bfloat16 l = __float2bfloat16(v - __bfloat162float(h));
    char* row = smem + SM_XS + n * XSTRIDE;
    *(__nv_bfloat16*)(row + d * 2)      = h;
    *(__nv_bfloat16*)(row + 64 + d * 2) = l;
  }

  // ---- build w0split(m0 -> buf0, m1 -> buf1) ----
#pragma unroll
  for (int mm = 0; mm < 2; ++mm) {
    const float* src = g_w0 + (size_t)(mbase + mm) * K_LENM;
    char* buf = smem + SM_W0S + mm * W0SBUF;
#pragma unroll
    for (int k = 0; k < 5; ++k) {
      int idx = tid + k * 256;
      if (idx < K_LENM) {
        float v = src[idx];
        int d = idx >> 6, h = idx & 63;
        __nv_bfloat16 hi = __float2bfloat16(v);
        __nv_bfloat16 lo = __float2bfloat16(v - __bfloat162float(hi));
        char* row = buf + h * XSTRIDE;
        *(__nv_bfloat16*)(row + d * 2)      = hi;
        *(__nv_bfloat16*)(row + 64 + d * 2) = lo;
      }
    }
  }
  __syncthreads();

  // ---- hoisted lane bases ----
  const uint32_t a1_base = sbase + SM_XS +
      (uint32_t)((wid * 16 + (lane & 15)) * XSTRIDE + ((lane >> 4) * 8) * 2);
  const uint32_t b1_off = (uint32_t)((lane & 7) * XSTRIDE + ((lane >> 3) * 8) * 2);
  const uint32_t b_base = sbase + SM_B +
      (uint32_t)((lane & 7) * ASTRIDE + ((lane >> 3) * 8) * 2);

  const int trow = lane >> 2;
  const int tcol = (lane & 3) * 2;

  // x fragments (m-invariant)
  uint32_t xa[2][2][4];
#pragma unroll
  for (int ap = 0; ap < 2; ++ap)
#pragma unroll
    for (int s = 0; s < 2; ++s)
      ldsm_x4(xa[ap][s][0], xa[ap][s][1], xa[ap][s][2], xa[ap][s][3],
              a1_base + (uint32_t)((ap * 2 + s) * 32));

  // prefetch w0(m2, m3)
  float pf[2][5];
#pragma unroll
  for (int mm = 0; mm < 2; ++mm) {
    const float* src = g_w0 + (size_t)(mbase + 2 + mm) * K_LENM;
#pragma unroll
    for (int k = 0; k < 5; ++k) {
      int idx = tid + k * 256;
      pf[mm][k] = src[idx < K_LENM ? idx : 0];
    }
  }

  const int nrow = n0 + wid * 16 + trow;
  float* const outp = out + (size_t)nrow * 10000u + (unsigned)mbase * 100u;

#pragma unroll 1
  for (int mi = 0; mi < 25; mi += 2) {
    const int have2 = (mi + 1 < 25);
    const int pidx = (mi >> 1) & 1;
    const uint32_t wb0 =
        sbase + SM_W0S + (uint32_t)((pidx * 2) * W0SBUF) + b1_off;
    const uint32_t wb1 = wb0 + W0SBUF;

    // ---- stage 1 for m0 and m1 ----
    uint32_t ah0[4][4], al0[4][4], ah1[4][4], al1[4][4];
    stage1_to_frags(wb0, xa, ah0, al0);
    if (have2) stage1_to_frags(wb1, xa, ah1, al1);

    // ---- publish w0split(m+2, m+3) into other pair ----
#pragma unroll
    for (int mm = 0; mm < 2; ++mm) {
      if (mi + 2 + mm < 25) {
        char* buf = smem + SM_W0S + ((1 - pidx) * 2 + mm) * W0SBUF;
#pragma unroll
        for (int k = 0; k < 5; ++k) {
          int idx = tid + k * 256;
          if (idx < K_LENM) {
            float v = pf[mm][k];
            int d = idx >> 6, h = idx & 63;
            __nv_bfloat16 hi = __float2bfloat16(v);
            __nv_bfloat16 lo = __float2bfloat16(v - __bfloat162float(hi));
            char* row = buf + h * XSTRIDE;
            *(__nv_bfloat16*)(row + d * 2)      = hi;
            *(__nv_bfloat16*)(row + 64 + d * 2) = lo;
          }
        }
      }
    }

    // ---- stage 2: B fragments loaded once per c-tile, used for both m ----
    float* const pm0 = outp + mi * 100;
#pragma unroll
    for (int j = 0; j < 13; ++j) {
      uint32_t bq[4][4];   // k0-31(h), k32-63(h), k64-95(l), k96-127(l)
#pragma unroll
      for (int s = 0; s < 4; ++s)
        ldsm_x4(bq[s][0], bq[s][1], bq[s][2], bq[s][3],
                b_base + (uint32_t)(j * 8 * ASTRIDE + s * 64));

      const int c = j * 8 + tcol;
      const float2 bv = *(const float2*)&bias_s[c];

      {
        float a0 = 0.0f, a1 = 0.0f, a2 = 0.0f, a3 = 0.0f;
        mma_bf16(a0,a1,a2,a3, ah0[0][0],ah0[0][1],ah0[0][2],ah0[0][3], bq[0][0],bq[0][1]);
        mma_bf16(a0,a1,a2,a3, ah0[1][0],ah0[1][1],ah0[1][2],ah0[1][3], bq[0][2],bq[0][3]);
        mma_bf16(a0,a1,a2,a3, ah0[2][0],ah0[2][1],ah0[2][2],ah0[2][3], bq[1][0],bq[1][1]);
        mma_bf16(a0,a1,a2,a3, ah0[3][0],ah0[3][1],ah0[3][2],ah0[3][3], bq[1][2],bq[1][3]);
        mma_bf16(a0,a1,a2,a3, al0[0][0],al0[0][1],al0[0][2],al0[0][3], bq[0][0],bq[0][1]);
        mma_bf16(a0,a1,a2,a3, al0[1][0],al0[1][1],al0[1][2],al0[1][3], bq[0][2],bq[0][3]);
        mma_bf16(a0,a1,a2,a3, al0[2][0],al0[2][1],al0[2][2],al0[2][3], bq[1][0],bq[1][1]);
        mma_bf16(a0,a1,a2,a3, al0[3][0],al0[3][1],al0[3][2],al0[3][3], bq[1][2],bq[1][3]);
        mma_bf16(a0,a1,a2,a3, ah0[0][0],ah0[0][1],ah0[0][2],ah0[0][3], bq[2][0],bq[2][1]);
        mma_bf16(a0,a1,a2,a3, ah0[1][0],ah0[1][1],ah0[1][2],ah0[1][3], bq[2][2],bq[2][3]);
        mma_bf16(a0,a1,a2,a3, ah0[2][0],ah0[2][1],ah0[2][2],ah0[2][3], bq[3][0],bq[3][1]);
        mma_bf16(a0,a1,a2,a3, ah0[3][0],ah0[3][1],ah0[3][2],ah0[3][3], bq[3][2],bq[3][3]);
        if (c < K_M) {
          *(float2*)(pm0 + c) = make_float2(a0 + bv.x, a1 + bv.y);
          *(float2*)(pm0 + 8 * 10000u + c) = make_float2(a2 + bv.x, a3 + bv.y);
        }
      }
      if (have2) {
        float a0 = 0.0f, a1 = 0.0f, a2 = 0.0f, a3 = 0.0f;
        mma_bf16(a0,a1,a2,a3, ah1[0][0],ah1[0][1],ah1[0][2],ah1[0][3], bq[0][0],bq[0][1]);
        mma_bf16(a0,a1,a2,a3, ah1[1][0],ah1[1][1],ah1[1][2],ah1[1][3], bq[0][2],bq[0][3]);
        mma_bf16(a0,a1,a2,a3, ah1[2][0],ah1[2][1],ah1[2][2],ah1[2][3], bq[1][0],bq[1][1]);
        mma_bf16(a0,a1,a2,a3, ah1[3][0],ah1[3][1],ah1[3][2],ah1[3][3], bq[1][2],bq[1][3]);
        mma_bf16(a0,a1,a2,a3, al1[0][0],al1[0][1],al1[0][2],al1[0][3], bq[0][0],bq[0][1]);
        mma_bf16(a0,a1,a2,a3, al1[1][0],al1[1][1],al1[1][2],al1[1][3], bq[0][2],bq[0][3]);
        mma_bf16(a0,a1,a2,a3, al1[2][0],al1[2][1],al1[2][2],al1[2][3], bq[1][0],bq[1][1]);
        mma_bf16(a0,a1,a2,a3, al1[3][0],al1[3][1],al1[3][2],al1[3][3], bq[1][2],bq[1][3]);
        mma_bf16(a0,a1,a2,a3, ah1[0][0],ah1[0][1],ah1[0][2],ah1[0][3], bq[2][0],bq[2][1]);
        mma_bf16(a0,a1,a2,a3, ah1[1][0],ah1[1][1],ah1[1][2],ah1[1][3], bq[2][2],bq[2][3]);
        mma_bf16(a0,a1,a2,a3, ah1[2][0],ah1[2][1],ah1[2][2],ah1[2][3], bq[3][0],bq[3][1]);
        mma_bf16(a0,a1,a2,a3, ah1[3][0],ah1[3][1],ah1[3][2],ah1[3][3], bq[3][2],bq[3][3]);
        if (c < K_M) {
          float* pm1 = pm0 + 100;
          *(float2*)(pm1 + c) = make_float2(a0 + bv.x, a1 + bv.y);
          *(float2*)(pm1 + 8 * 10000u + c) = make_float2(a2 + bv.x, a3 + bv.y);
        }
      }
    }

    // ---- prefetch w0(m+4, m+5): latency hidden by barrier+stage-1 ----
#pragma unroll
    for (int mm = 0; mm < 2; ++mm) {
      if (mi + 4 + mm < 25) {
        const float* src = g_w0 + (size_t)(mbase + mi + 4 + mm) * K_LENM;
#pragma unroll
        for (int k = 0; k < 5; ++k) {
          int idx = tid + k * 256;
          pf[mm][k] = src[idx < K_LENM ? idx : 0];
        }
      }
    }

    __syncthreads();   // w0split pair handoff
  }
}

// ---------------------------------------------------------------------
extern "C" void kernel_launch(void* const* d_in, const int* in_sizes, int n_in,
                              void* d_out, int out_size) {
  const float* x  = (const float*)d_in[0];
  const float* ms = (const float*)d_in[1];
  if (n_in >= 2 && in_sizes[0] == 2306) {
    x  = (const float*)d_in[1];
    ms = (const float*)d_in[0];
  }
  float* out = (float*)d_out;

  setup_kernel<<<(K_LENM * K_M + 255) / 256, 256>>>(ms, out, out_size);

  cudaFuncSetAttribute(pred_kernel,
                       cudaFuncAttributeMaxDynamicSharedMemorySize, SM_TOTAL);
  dim3 grid(K_N / 128, 4);
  pred_kernel<<<grid, 256, SM_TOTAL>>>(x, out);
}